// round 14
// baseline (speedup 1.0000x reference)
#include <cuda_runtime.h>
#include <cuda_bf16.h>
#include <cstdint>

// ---------------- Problem constants ----------------
#define M_TOK   32768      // B*S = 4*8192
#define KDIM    2048
#define NDIM    2048

// ---------------- Scratch (device globals; no allocation allowed) ----------------
__device__ __align__(256) static __nv_bfloat16 g_xq[(size_t)M_TOK * KDIM]; // 128 MB quantized activations (integer-valued bf16)
__device__ __align__(256) static __nv_bfloat16 g_wq[(size_t)NDIM * KDIM];  // 8 MB ternary weights (bf16 -1/0/1)
__device__ static float g_inva[M_TOK];   // per-token dequant scale 1/a_scale
__device__ static float g_rowabs[NDIM];  // per-row |W| sums
__device__ static float g_ws[2];         // [0] = w_scale, [1] = 1/w_scale = mean|W|+eps

// ---------------- Reductions ----------------
__device__ __forceinline__ float warp_sum(float v) {
#pragma unroll
    for (int o = 16; o; o >>= 1) v += __shfl_xor_sync(0xffffffffu, v, o);
    return v;
}
__device__ __forceinline__ float warp_max(float v) {
#pragma unroll
    for (int o = 16; o; o >>= 1) v = fmaxf(v, __shfl_xor_sync(0xffffffffu, v, o));
    return v;
}

// ---------------- Weight quantization ----------------
__global__ __launch_bounds__(256) void w_rowabs_kernel(const float* __restrict__ W) {
    int row = blockIdx.x, tid = threadIdx.x;
    const float4* wr = reinterpret_cast<const float4*>(W + (size_t)row * KDIM);
    float4 a = wr[2 * tid], b = wr[2 * tid + 1];
    float s = fabsf(a.x) + fabsf(a.y) + fabsf(a.z) + fabsf(a.w)
            + fabsf(b.x) + fabsf(b.y) + fabsf(b.z) + fabsf(b.w);
    s = warp_sum(s);
    __shared__ float ws[8];
    if (!(tid & 31)) ws[tid >> 5] = s;
    __syncthreads();
    if (tid == 0) {
        float t = 0.f;
#pragma unroll
        for (int i = 0; i < 8; i++) t += ws[i];
        g_rowabs[row] = t;
    }
}

__global__ __launch_bounds__(256) void w_scale_kernel() {
    int tid = threadIdx.x;
    float s = 0.f;
    for (int i = tid; i < NDIM; i += 256) s += g_rowabs[i];
    s = warp_sum(s);
    __shared__ float ws[8];
    if (!(tid & 31)) ws[tid >> 5] = s;
    __syncthreads();
    if (tid == 0) {
        float t = 0.f;
#pragma unroll
        for (int i = 0; i < 8; i++) t += ws[i];
        float mean = t * (1.0f / ((float)NDIM * (float)KDIM));
        g_ws[0] = 1.0f / (mean + 1e-5f);  // w_scale
        g_ws[1] = mean + 1e-5f;           // 1/w_scale
    }
}

__global__ __launch_bounds__(256) void w_quant_kernel(const float* __restrict__ W) {
    float wsc = g_ws[0];
    int i = blockIdx.x * 256 + threadIdx.x;  // over 1M float4
    float4 v = reinterpret_cast<const float4*>(W)[i];
    union { uint2 u; __nv_bfloat16 h[4]; } pk;
    pk.h[0] = __float2bfloat16(fminf(fmaxf(rintf(v.x * wsc), -1.f), 1.f));
    pk.h[1] = __float2bfloat16(fminf(fmaxf(rintf(v.y * wsc), -1.f), 1.f));
    pk.h[2] = __float2bfloat16(fminf(fmaxf(rintf(v.z * wsc), -1.f), 1.f));
    pk.h[3] = __float2bfloat16(fminf(fmaxf(rintf(v.w * wsc), -1.f), 1.f));
    reinterpret_cast<uint2*>(g_wq)[i] = pk.u;
}

// ---------------- Activation RMSNorm + int8 fake-quant ----------------
// 128 threads/token, 4x float4 per thread -> 8 independent LDG.128 in
// flight (MLP 8 vs old 2): pushes DRAM utilization toward the roofline.
__global__ __launch_bounds__(128) void act_quant_kernel(const float* __restrict__ x,
                                                        const float* __restrict__ gamma) {
    int token = blockIdx.x;
    int tid = threadIdx.x;
    const float4* xr = reinterpret_cast<const float4*>(x + (size_t)token * KDIM);
    const float4* gr = reinterpret_cast<const float4*>(gamma);

    float4 v[4], g4[4];
#pragma unroll
    for (int i = 0; i < 4; i++) v[i] = xr[tid + 128 * i];
#pragma unroll
    for (int i = 0; i < 4; i++) g4[i] = gr[tid + 128 * i];

    float xg[16];
    float ss = 0.f, am = 0.f;
#pragma unroll
    for (int i = 0; i < 4; i++) {
        xg[4 * i + 0] = v[i].x * g4[i].x;
        xg[4 * i + 1] = v[i].y * g4[i].y;
        xg[4 * i + 2] = v[i].z * g4[i].z;
        xg[4 * i + 3] = v[i].w * g4[i].w;
        ss += v[i].x * v[i].x + v[i].y * v[i].y + v[i].z * v[i].z + v[i].w * v[i].w;
        am = fmaxf(am, fmaxf(fmaxf(fabsf(xg[4 * i + 0]), fabsf(xg[4 * i + 1])),
                             fmaxf(fabsf(xg[4 * i + 2]), fabsf(xg[4 * i + 3]))));
    }

    ss = warp_sum(ss);
    am = warp_max(am);
    __shared__ float sss[4], sam[4], sbr[2];
    int wid = tid >> 5, lid = tid & 31;
    if (!lid) { sss[wid] = ss; sam[wid] = am; }
    __syncthreads();
    if (tid == 0) {
        float S = 0.f, A = 0.f;
#pragma unroll
        for (int i = 0; i < 4; i++) { S += sss[i]; A = fmaxf(A, sam[i]); }
        float rms = 1.0f / sqrtf(S * (1.0f / (float)KDIM) + 1e-6f);
        float ascale = 127.0f / (A * rms + 1e-5f);
        sbr[0] = rms; sbr[1] = ascale;
        g_inva[token] = 1.0f / ascale;
    }
    __syncthreads();
    float rms = sbr[0], asc = sbr[1];
    uint2* outp = reinterpret_cast<uint2*>(g_xq + (size_t)token * KDIM);
#pragma unroll
    for (int i = 0; i < 4; i++) {
        union { uint2 u; __nv_bfloat16 h[4]; } pk;
#pragma unroll
        for (int j = 0; j < 4; j++) {
            float q = rintf(xg[4 * i + j] * rms * asc);   // round-half-to-even = jnp.round
            q = fminf(fmaxf(q, -128.0f), 127.0f);
            pk.h[j] = __float2bfloat16(q);                 // exact: |q| <= 128
        }
        outp[tid + 128 * i] = pk.u;
    }
}

// =====================================================================
// GEMM: 128x128 CTA tile, BK=64 bf16 (128B SW128 rows), legacy HMMA
// m16n8k16, 8 warps = 4(M) x 2(N), warp tile 32x64, 2 CTAs/SM —
// the proven 708us structure (R5), with ONE change: the next chunk's
// 8 cp.async are issued 2-per-ks-slice after each slice's LDSM group,
// smoothing the post-barrier LSU burst without reordering LDSM->MMA.
// =====================================================================
#define BK 64                   // bf16 per K chunk (128 bytes, SW128 atom)
#define NK_ITERS (KDIM / BK)    // 32
#define A_BYTES 16384           // 128 rows x 128B
#define B_BYTES 16384
#define STAGE_BYTES (A_BYTES + B_BYTES)  // 32768
static constexpr unsigned GEMM_SMEM = 2 * STAGE_BYTES;  // 65536

__device__ __forceinline__ uint32_t smem_u32(const void* p) {
    uint32_t a;
    asm("{ .reg .u64 t; cvta.to.shared.u64 t, %1; cvt.u32.u64 %0, t; }" : "=r"(a) : "l"(p));
    return a;
}

__device__ __forceinline__ void cp_async16(uint32_t saddr, const void* gaddr) {
    asm volatile("cp.async.cg.shared.global [%0], [%1], 16;" :: "r"(saddr), "l"(gaddr));
}
__device__ __forceinline__ void cp_commit() { asm volatile("cp.async.commit_group;"); }
__device__ __forceinline__ void cp_wait_all() { asm volatile("cp.async.wait_group 0;"); }

__device__ __forceinline__ void ldmatrix_x4(uint32_t* r, uint32_t addr) {
    asm volatile("ldmatrix.sync.aligned.m8n8.x4.shared.b16 {%0,%1,%2,%3}, [%4];"
                 : "=r"(r[0]), "=r"(r[1]), "=r"(r[2]), "=r"(r[3]) : "r"(addr));
}

__device__ __forceinline__ void mma16816(float* d, const uint32_t* a, uint32_t b0, uint32_t b1) {
    asm volatile(
        "mma.sync.aligned.m16n8k16.row.col.f32.bf16.bf16.f32 "
        "{%0,%1,%2,%3}, {%4,%5,%6,%7}, {%8,%9}, {%0,%1,%2,%3};"
        : "+f"(d[0]), "+f"(d[1]), "+f"(d[2]), "+f"(d[3])
        : "r"(a[0]), "r"(a[1]), "r"(a[2]), "r"(a[3]), "r"(b0), "r"(b1));
}

__global__ __launch_bounds__(256, 2) void bitlinear_gemm(float* __restrict__ out) {
    extern __shared__ char smem[];
    const uint32_t base = smem_u32(smem);

    const int tid = threadIdx.x;
    const int wid = tid >> 5;
    const uint32_t lane = tid & 31;
    const int warp_m = wid >> 1;          // 0..3
    const int warp_n = wid & 1;           // 0..1
    const size_t tile_m = (size_t)blockIdx.y * 128;
    const size_t tile_n = (size_t)blockIdx.x * 128;

    const char* gA = reinterpret_cast<const char*>(g_xq) + tile_m * (KDIM * 2);
    const char* gB = reinterpret_cast<const char*>(g_wq) + tile_n * (KDIM * 2);

    // ---- loader precompute: A = 1024 16B units (4/thread), B same ----
    uint32_t st_sw[8];
    const char* gsrc[8];
#pragma unroll
    for (int j = 0; j < 4; j++) {
        int u = tid + j * 256;
        int row = u >> 3, q = u & 7;
        uint32_t off = (uint32_t)row * 128u + (uint32_t)q * 16u;
        uint32_t sw = off ^ ((off >> 3) & 0x70u);
        st_sw[j] = sw;
        st_sw[j + 4] = (uint32_t)A_BYTES + sw;
        gsrc[j]     = gA + (size_t)row * (KDIM * 2) + (size_t)q * 16u;
        gsrc[j + 4] = gB + (size_t)row * (KDIM * 2) + (size_t)q * 16u;
    }

    // ---- ldmatrix base offsets (per lane) ----
    const uint32_t lrow = lane & 15;
    const uint32_t lcol = (lane >> 4) * 16;   // byte offset of 8-col half
    const uint32_t a_off0 = ((uint32_t)warp_m * 32u + lrow) * 128u + lcol;
    const uint32_t b_off0 = ((uint32_t)warp_n * 64u + lrow) * 128u + lcol;

    float acc[2][8][4];
#pragma unroll
    for (int mi = 0; mi < 2; mi++)
#pragma unroll
        for (int nj = 0; nj < 8; nj++)
#pragma unroll
            for (int i = 0; i < 4; i++) acc[mi][nj][i] = 0.f;

    // prologue: load chunk 0 into buffer 0
    {
        uint32_t sb = base;
#pragma unroll
        for (int j = 0; j < 8; j++) cp_async16(sb + st_sw[j], gsrc[j]);
        cp_commit();
    }

    for (int c = 0; c < NK_ITERS; ++c) {
        int buf = c & 1;
        cp_wait_all();
        __syncthreads();   // chunk c visible; all warps done with buffer buf^1

        uint32_t sb = base + (uint32_t)buf * STAGE_BYTES;
        uint32_t nsb = base + (uint32_t)(buf ^ 1) * STAGE_BYTES;
        size_t ncb = (size_t)(c + 1) * 128;
        bool more = (c + 1 < NK_ITERS);

#pragma unroll
        for (int ks = 0; ks < 4; ks++) {
            uint32_t kb = (uint32_t)ks * 32u;     // 16 bf16 = 32 bytes
            uint32_t af[2][4], bf[4][4];
#pragma unroll
            for (int mi = 0; mi < 2; mi++) {
                uint32_t off = a_off0 + (uint32_t)mi * 2048u + kb;
                ldmatrix_x4(af[mi], sb + (off ^ ((off >> 3) & 0x70u)));
            }
#pragma unroll
            for (int nj = 0; nj < 4; nj++) {
                uint32_t off = b_off0 + (uint32_t)nj * 2048u + kb;
                ldmatrix_x4(bf[nj], sb + (uint32_t)A_BYTES + (off ^ ((off >> 3) & 0x70u)));
            }
            // spread next-chunk cp.async: 2 per slice, after this slice's LDSMs
            if (more) {
                cp_async16(nsb + st_sw[2 * ks + 0], gsrc[2 * ks + 0] + ncb);
                cp_async16(nsb + st_sw[2 * ks + 1], gsrc[2 * ks + 1] + ncb);
                if (ks == 3) cp_commit();
            }
#pragma unroll
            for (int mi = 0; mi < 2; mi++)
#pragma unroll
                for (int nj = 0; nj < 4; nj++) {
                    mma16816(acc[mi][nj * 2 + 0], af[mi], bf[nj][0], bf[nj][2]);
                    mma16816(acc[mi][nj * 2 + 1], af[mi], bf[nj][1], bf[nj][3]);
                }
        }
    }

    // ---- epilogue: dequant scale + store fp32 ----
    const float invw = g_ws[1];
    const int g = lane >> 2, cc = lane & 3;
#pragma unroll
    for (int mi = 0; mi < 2; mi++) {
        size_t r0 = tile_m + (size_t)(warp_m * 32 + mi * 16 + g);
        size_t r1 = r0 + 8;
        float s0 = g_inva[r0] * invw;
        float s1 = g_inva[r1] * invw;
        float* p0 = out + r0 * NDIM + tile_n + (size_t)(warp_n * 64 + cc * 2);
        float* p1 = out + r1 * NDIM + tile_n + (size_t)(warp_n * 64 + cc * 2);
#pragma unroll
        for (int nj = 0; nj < 8; nj++) {
            float2 v0 = make_float2(acc[mi][nj][0] * s0, acc[mi][nj][1] * s0);
            float2 v1 = make_float2(acc[mi][nj][2] * s1, acc[mi][nj][3] * s1);
            *reinterpret_cast<float2*>(p0 + nj * 8) = v0;
            *reinterpret_cast<float2*>(p1 + nj * 8) = v1;
        }
    }
}

// ---------------- Launch ----------------
extern "C" void kernel_launch(void* const* d_in, const int* in_sizes, int n_in,
                              void* d_out, int out_size) {
    const float* x     = reinterpret_cast<const float*>(d_in[0]);  // [4,8192,2048] fp32
    const float* gamma = reinterpret_cast<const float*>(d_in[1]);  // [2048] fp32
    const float* W     = reinterpret_cast<const float*>(d_in[2]);  // [2048,2048] fp32
    float* out = reinterpret_cast<float*>(d_out);

    cudaFuncSetAttribute(bitlinear_gemm, cudaFuncAttributeMaxDynamicSharedMemorySize, (int)GEMM_SMEM);

    w_rowabs_kernel<<<NDIM, 256>>>(W);
    w_scale_kernel<<<1, 256>>>();
    w_quant_kernel<<<(NDIM * KDIM) / (256 * 4), 256>>>(W);
    act_quant_kernel<<<M_TOK, 128>>>(x, gamma);

    dim3 grid(NDIM / 128, M_TOK / 128);  // (16, 256), x-fastest for A reuse in L2
    bitlinear_gemm<<<grid, 256, GEMM_SMEM>>>(out);
}

// round 15
// speedup vs baseline: 1.1214x; 1.1214x over previous
#include <cuda_runtime.h>
#include <cuda_bf16.h>
#include <cstdint>

// ---------------- Problem constants ----------------
#define M_TOK   32768      // B*S = 4*8192
#define KDIM    2048
#define NDIM    2048

// ---------------- Scratch (device globals; no allocation allowed) ----------------
__device__ __align__(256) static __nv_bfloat16 g_xq[(size_t)M_TOK * KDIM]; // 128 MB quantized activations (integer-valued bf16)
__device__ __align__(256) static __nv_bfloat16 g_wq[(size_t)NDIM * KDIM];  // 8 MB ternary weights (bf16 -1/0/1)
__device__ static float g_inva[M_TOK];   // per-token dequant scale 1/a_scale
__device__ static float g_rowabs[NDIM];  // per-row |W| sums
__device__ static float g_ws[2];         // [0] = w_scale, [1] = 1/w_scale = mean|W|+eps

// ---------------- Reductions ----------------
__device__ __forceinline__ float warp_sum(float v) {
#pragma unroll
    for (int o = 16; o; o >>= 1) v += __shfl_xor_sync(0xffffffffu, v, o);
    return v;
}
__device__ __forceinline__ float warp_max(float v) {
#pragma unroll
    for (int o = 16; o; o >>= 1) v = fmaxf(v, __shfl_xor_sync(0xffffffffu, v, o));
    return v;
}

// ---------------- Weight quantization ----------------
__global__ __launch_bounds__(256) void w_rowabs_kernel(const float* __restrict__ W) {
    int row = blockIdx.x, tid = threadIdx.x;
    const float4* wr = reinterpret_cast<const float4*>(W + (size_t)row * KDIM);
    float4 a = wr[2 * tid], b = wr[2 * tid + 1];
    float s = fabsf(a.x) + fabsf(a.y) + fabsf(a.z) + fabsf(a.w)
            + fabsf(b.x) + fabsf(b.y) + fabsf(b.z) + fabsf(b.w);
    s = warp_sum(s);
    __shared__ float ws[8];
    if (!(tid & 31)) ws[tid >> 5] = s;
    __syncthreads();
    if (tid == 0) {
        float t = 0.f;
#pragma unroll
        for (int i = 0; i < 8; i++) t += ws[i];
        g_rowabs[row] = t;
    }
}

__global__ __launch_bounds__(256) void w_scale_kernel() {
    int tid = threadIdx.x;
    float s = 0.f;
    for (int i = tid; i < NDIM; i += 256) s += g_rowabs[i];
    s = warp_sum(s);
    __shared__ float ws[8];
    if (!(tid & 31)) ws[tid >> 5] = s;
    __syncthreads();
    if (tid == 0) {
        float t = 0.f;
#pragma unroll
        for (int i = 0; i < 8; i++) t += ws[i];
        float mean = t * (1.0f / ((float)NDIM * (float)KDIM));
        g_ws[0] = 1.0f / (mean + 1e-5f);  // w_scale
        g_ws[1] = mean + 1e-5f;           // 1/w_scale
    }
}

__global__ __launch_bounds__(256) void w_quant_kernel(const float* __restrict__ W) {
    float wsc = g_ws[0];
    int i = blockIdx.x * 256 + threadIdx.x;  // over 1M float4
    float4 v = reinterpret_cast<const float4*>(W)[i];
    union { uint2 u; __nv_bfloat16 h[4]; } pk;
    pk.h[0] = __float2bfloat16(fminf(fmaxf(rintf(v.x * wsc), -1.f), 1.f));
    pk.h[1] = __float2bfloat16(fminf(fmaxf(rintf(v.y * wsc), -1.f), 1.f));
    pk.h[2] = __float2bfloat16(fminf(fmaxf(rintf(v.z * wsc), -1.f), 1.f));
    pk.h[3] = __float2bfloat16(fminf(fmaxf(rintf(v.w * wsc), -1.f), 1.f));
    reinterpret_cast<uint2*>(g_wq)[i] = pk.u;
}

// ---------------- Activation RMSNorm + int8 fake-quant ----------------
// 2 tokens per 256-thread block (128 threads/token, 4x float4 each):
// MLP=8 independent LDG.128 per thread (R14-proven) + 8 warps/block to
// restore occupancy lost at 4-warp blocks. Per-token math bit-identical.
__global__ __launch_bounds__(256) void act_quant_kernel(const float* __restrict__ x,
                                                        const float* __restrict__ gamma) {
    const int half = threadIdx.x >> 7;            // 0 or 1: which token
    const int tid  = threadIdx.x & 127;           // lane within token
    const int token = blockIdx.x * 2 + half;
    const float4* xr = reinterpret_cast<const float4*>(x + (size_t)token * KDIM);
    const float4* gr = reinterpret_cast<const float4*>(gamma);

    float4 v[4], g4[4];
#pragma unroll
    for (int i = 0; i < 4; i++) v[i] = xr[tid + 128 * i];
#pragma unroll
    for (int i = 0; i < 4; i++) g4[i] = gr[tid + 128 * i];

    float xg[16];
    float ss = 0.f, am = 0.f;
#pragma unroll
    for (int i = 0; i < 4; i++) {
        xg[4 * i + 0] = v[i].x * g4[i].x;
        xg[4 * i + 1] = v[i].y * g4[i].y;
        xg[4 * i + 2] = v[i].z * g4[i].z;
        xg[4 * i + 3] = v[i].w * g4[i].w;
        ss += v[i].x * v[i].x + v[i].y * v[i].y + v[i].z * v[i].z + v[i].w * v[i].w;
        am = fmaxf(am, fmaxf(fmaxf(fabsf(xg[4 * i + 0]), fabsf(xg[4 * i + 1])),
                             fmaxf(fabsf(xg[4 * i + 2]), fabsf(xg[4 * i + 3]))));
    }

    ss = warp_sum(ss);
    am = warp_max(am);
    __shared__ float sss[2][4], sam[2][4], sbr[2][2];
    int wid = tid >> 5, lid = tid & 31;
    if (!lid) { sss[half][wid] = ss; sam[half][wid] = am; }
    __syncthreads();
    if (tid == 0) {
        float S = 0.f, A = 0.f;
#pragma unroll
        for (int i = 0; i < 4; i++) { S += sss[half][i]; A = fmaxf(A, sam[half][i]); }
        float rms = 1.0f / sqrtf(S * (1.0f / (float)KDIM) + 1e-6f);
        float ascale = 127.0f / (A * rms + 1e-5f);
        sbr[half][0] = rms; sbr[half][1] = ascale;
        g_inva[token] = 1.0f / ascale;
    }
    __syncthreads();
    float rms = sbr[half][0], asc = sbr[half][1];
    uint2* outp = reinterpret_cast<uint2*>(g_xq + (size_t)token * KDIM);
#pragma unroll
    for (int i = 0; i < 4; i++) {
        union { uint2 u; __nv_bfloat16 h[4]; } pk;
#pragma unroll
        for (int j = 0; j < 4; j++) {
            float q = rintf(xg[4 * i + j] * rms * asc);   // round-half-to-even = jnp.round
            q = fminf(fmaxf(q, -128.0f), 127.0f);
            pk.h[j] = __float2bfloat16(q);                 // exact: |q| <= 128
        }
        outp[tid + 128 * i] = pk.u;
    }
}

// =====================================================================
// GEMM: byte-identical to the proven 708us R5 kernel.
// 128x128 CTA tile, BK=64 bf16 (128B SW128 rows), legacy HMMA
// m16n8k16, 8 warps = 4(M) x 2(N), warp tile 32x64, 2 CTAs/SM,
// 2-stage cp.async (single burst right after the barrier), plain
// LDSM-group -> MMA-group order (ptxas schedules this best; every
// manual reordering attempt regressed: R13 -19us, R14 -90us).
// =====================================================================
#define BK 64                   // bf16 per K chunk (128 bytes, SW128 atom)
#define NK_ITERS (KDIM / BK)    // 32
#define A_BYTES 16384           // 128 rows x 128B
#define B_BYTES 16384
#define STAGE_BYTES (A_BYTES + B_BYTES)  // 32768
static constexpr unsigned GEMM_SMEM = 2 * STAGE_BYTES;  // 65536

__device__ __forceinline__ uint32_t smem_u32(const void* p) {
    uint32_t a;
    asm("{ .reg .u64 t; cvta.to.shared.u64 t, %1; cvt.u32.u64 %0, t; }" : "=r"(a) : "l"(p));
    return a;
}

__device__ __forceinline__ void cp_async16(uint32_t saddr, const void* gaddr) {
    asm volatile("cp.async.cg.shared.global [%0], [%1], 16;" :: "r"(saddr), "l"(gaddr));
}
__device__ __forceinline__ void cp_commit() { asm volatile("cp.async.commit_group;"); }
__device__ __forceinline__ void cp_wait_all() { asm volatile("cp.async.wait_group 0;"); }

__device__ __forceinline__ void ldmatrix_x4(uint32_t* r, uint32_t addr) {
    asm volatile("ldmatrix.sync.aligned.m8n8.x4.shared.b16 {%0,%1,%2,%3}, [%4];"
                 : "=r"(r[0]), "=r"(r[1]), "=r"(r[2]), "=r"(r[3]) : "r"(addr));
}

__device__ __forceinline__ void mma16816(float* d, const uint32_t* a, uint32_t b0, uint32_t b1) {
    asm volatile(
        "mma.sync.aligned.m16n8k16.row.col.f32.bf16.bf16.f32 "
        "{%0,%1,%2,%3}, {%4,%5,%6,%7}, {%8,%9}, {%0,%1,%2,%3};"
        : "+f"(d[0]), "+f"(d[1]), "+f"(d[2]), "+f"(d[3])
        : "r"(a[0]), "r"(a[1]), "r"(a[2]), "r"(a[3]), "r"(b0), "r"(b1));
}

__global__ __launch_bounds__(256, 2) void bitlinear_gemm(float* __restrict__ out) {
    extern __shared__ char smem[];
    const uint32_t base = smem_u32(smem);

    const int tid = threadIdx.x;
    const int wid = tid >> 5;
    const uint32_t lane = tid & 31;
    const int warp_m = wid >> 1;          // 0..3
    const int warp_n = wid & 1;           // 0..1
    const size_t tile_m = (size_t)blockIdx.y * 128;
    const size_t tile_n = (size_t)blockIdx.x * 128;

    const char* gA = reinterpret_cast<const char*>(g_xq) + tile_m * (KDIM * 2);
    const char* gB = reinterpret_cast<const char*>(g_wq) + tile_n * (KDIM * 2);

    // ---- loader precompute: A = 1024 16B units (4/thread), B same ----
    uint32_t st_sw[8];
    const char* gsrc[8];
#pragma unroll
    for (int j = 0; j < 4; j++) {
        int u = tid + j * 256;
        int row = u >> 3, q = u & 7;
        uint32_t off = (uint32_t)row * 128u + (uint32_t)q * 16u;
        uint32_t sw = off ^ ((off >> 3) & 0x70u);
        st_sw[j] = sw;                                  // A region (+0)
        st_sw[j + 4] = 16384u + sw;                     // B region (+16KB)
        gsrc[j]     = gA + (size_t)row * (KDIM * 2) + (size_t)q * 16u;
        gsrc[j + 4] = gB + (size_t)row * (KDIM * 2) + (size_t)q * 16u;
    }

    auto load_chunk = [&](int c, int buf) {
        uint32_t sb = base + (uint32_t)buf * STAGE_BYTES;
        size_t cb = (size_t)c * 128;
#pragma unroll
        for (int j = 0; j < 8; j++) cp_async16(sb + st_sw[j], gsrc[j] + cb);
        cp_commit();
    };

    // ---- ldmatrix base offsets (per lane) ----
    const uint32_t lrow = lane & 15;
    const uint32_t lcol = (lane >> 4) * 16;   // byte offset of 8-col half
    const uint32_t a_off0 = ((uint32_t)warp_m * 32u + lrow) * 128u + lcol;
    const uint32_t b_off0 = ((uint32_t)warp_n * 64u + lrow) * 128u + lcol;

    float acc[2][8][4];
#pragma unroll
    for (int mi = 0; mi < 2; mi++)
#pragma unroll
        for (int nj = 0; nj < 8; nj++)
#pragma unroll
            for (int i = 0; i < 4; i++) acc[mi][nj][i] = 0.f;

    load_chunk(0, 0);

    for (int c = 0; c < NK_ITERS; ++c) {
        int buf = c & 1;
        cp_wait_all();
        __syncthreads();
        if (c + 1 < NK_ITERS) load_chunk(c + 1, buf ^ 1);

        uint32_t sb = base + (uint32_t)buf * STAGE_BYTES;
#pragma unroll
        for (int ks = 0; ks < 4; ks++) {
            uint32_t kb = (uint32_t)ks * 32u;     // 16 bf16 = 32 bytes
            uint32_t af[2][4], bf[4][4];
#pragma unroll
            for (int mi = 0; mi < 2; mi++) {
                uint32_t off = a_off0 + (uint32_t)mi * 2048u + kb;
                ldmatrix_x4(af[mi], sb + (off ^ ((off >> 3) & 0x70u)));
            }
#pragma unroll
            for (int nj = 0; nj < 4; nj++) {
                uint32_t off = b_off0 + (uint32_t)nj * 2048u + kb;
                ldmatrix_x4(bf[nj], sb + 16384u + (off ^ ((off >> 3) & 0x70u)));
            }
#pragma unroll
            for (int mi = 0; mi < 2; mi++)
#pragma unroll
                for (int nj = 0; nj < 4; nj++) {
                    mma16816(acc[mi][nj * 2 + 0], af[mi], bf[nj][0], bf[nj][2]);
                    mma16816(acc[mi][nj * 2 + 1], af[mi], bf[nj][1], bf[nj][3]);
                }
        }
        __syncthreads();
    }

    // ---- epilogue: dequant scale + store fp32 ----
    const float invw = g_ws[1];
    const int g = lane >> 2, cc = lane & 3;
#pragma unroll
    for (int mi = 0; mi < 2; mi++) {
        size_t r0 = tile_m + (size_t)(warp_m * 32 + mi * 16 + g);
        size_t r1 = r0 + 8;
        float s0 = g_inva[r0] * invw;
        float s1 = g_inva[r1] * invw;
        float* p0 = out + r0 * NDIM + tile_n + (size_t)(warp_n * 64 + cc * 2);
        float* p1 = out + r1 * NDIM + tile_n + (size_t)(warp_n * 64 + cc * 2);
#pragma unroll
        for (int nj = 0; nj < 8; nj++) {
            float2 v0 = make_float2(acc[mi][nj][0] * s0, acc[mi][nj][1] * s0);
            float2 v1 = make_float2(acc[mi][nj][2] * s1, acc[mi][nj][3] * s1);
            *reinterpret_cast<float2*>(p0 + nj * 8) = v0;
            *reinterpret_cast<float2*>(p1 + nj * 8) = v1;
        }
    }
}

// ---------------- Launch ----------------
extern "C" void kernel_launch(void* const* d_in, const int* in_sizes, int n_in,
                              void* d_out, int out_size) {
    const float* x     = reinterpret_cast<const float*>(d_in[0]);  // [4,8192,2048] fp32
    const float* gamma = reinterpret_cast<const float*>(d_in[1]);  // [2048] fp32
    const float* W     = reinterpret_cast<const float*>(d_in[2]);  // [2048,2048] fp32
    float* out = reinterpret_cast<float*>(d_out);

    cudaFuncSetAttribute(bitlinear_gemm, cudaFuncAttributeMaxDynamicSharedMemorySize, (int)GEMM_SMEM);

    w_rowabs_kernel<<<NDIM, 256>>>(W);
    w_scale_kernel<<<1, 256>>>();
    w_quant_kernel<<<(NDIM * KDIM) / (256 * 4), 256>>>(W);
    act_quant_kernel<<<M_TOK / 2, 256>>>(x, gamma);

    dim3 grid(NDIM / 128, M_TOK / 128);  // (16, 256), x-fastest for A reuse in L2
    bitlinear_gemm<<<grid, 256, GEMM_SMEM>>>(out);
}

// round 16
// speedup vs baseline: 1.1321x; 1.0096x over previous
#include <cuda_runtime.h>
#include <cuda_bf16.h>
#include <cstdint>

// ---------------- Problem constants ----------------
#define M_TOK   32768      // B*S = 4*8192
#define KDIM    2048
#define NDIM    2048

// ---------------- Scratch (device globals; no allocation allowed) ----------------
__device__ __align__(256) static __nv_bfloat16 g_xq[(size_t)M_TOK * KDIM]; // 128 MB quantized activations (integer-valued bf16)
__device__ __align__(256) static __nv_bfloat16 g_wq[(size_t)NDIM * KDIM];  // 8 MB ternary weights (bf16 -1/0/1)
__device__ static float g_inva[M_TOK];   // per-token dequant scale 1/a_scale
__device__ static float g_rowabs[NDIM];  // per-row |W| sums
__device__ static float g_ws[2];         // [0] = w_scale, [1] = 1/w_scale = mean|W|+eps

// ---------------- Reductions ----------------
__device__ __forceinline__ float warp_sum(float v) {
#pragma unroll
    for (int o = 16; o; o >>= 1) v += __shfl_xor_sync(0xffffffffu, v, o);
    return v;
}
__device__ __forceinline__ float warp_max(float v) {
#pragma unroll
    for (int o = 16; o; o >>= 1) v = fmaxf(v, __shfl_xor_sync(0xffffffffu, v, o));
    return v;
}

// ---------------- Weight quantization ----------------
__global__ __launch_bounds__(256) void w_rowabs_kernel(const float* __restrict__ W) {
    int row = blockIdx.x, tid = threadIdx.x;
    const float4* wr = reinterpret_cast<const float4*>(W + (size_t)row * KDIM);
    float4 a = wr[2 * tid], b = wr[2 * tid + 1];
    float s = fabsf(a.x) + fabsf(a.y) + fabsf(a.z) + fabsf(a.w)
            + fabsf(b.x) + fabsf(b.y) + fabsf(b.z) + fabsf(b.w);
    s = warp_sum(s);
    __shared__ float ws[8];
    if (!(tid & 31)) ws[tid >> 5] = s;
    __syncthreads();
    if (tid == 0) {
        float t = 0.f;
#pragma unroll
        for (int i = 0; i < 8; i++) t += ws[i];
        g_rowabs[row] = t;
    }
}

__global__ __launch_bounds__(256) void w_scale_kernel() {
    int tid = threadIdx.x;
    float s = 0.f;
    for (int i = tid; i < NDIM; i += 256) s += g_rowabs[i];
    s = warp_sum(s);
    __shared__ float ws[8];
    if (!(tid & 31)) ws[tid >> 5] = s;
    __syncthreads();
    if (tid == 0) {
        float t = 0.f;
#pragma unroll
        for (int i = 0; i < 8; i++) t += ws[i];
        float mean = t * (1.0f / ((float)NDIM * (float)KDIM));
        g_ws[0] = 1.0f / (mean + 1e-5f);  // w_scale
        g_ws[1] = mean + 1e-5f;           // 1/w_scale
    }
}

__global__ __launch_bounds__(256) void w_quant_kernel(const float* __restrict__ W) {
    float wsc = g_ws[0];
    int i = blockIdx.x * 256 + threadIdx.x;  // over 1M float4
    float4 v = reinterpret_cast<const float4*>(W)[i];
    union { uint2 u; __nv_bfloat16 h[4]; } pk;
    pk.h[0] = __float2bfloat16(fminf(fmaxf(rintf(v.x * wsc), -1.f), 1.f));
    pk.h[1] = __float2bfloat16(fminf(fmaxf(rintf(v.y * wsc), -1.f), 1.f));
    pk.h[2] = __float2bfloat16(fminf(fmaxf(rintf(v.z * wsc), -1.f), 1.f));
    pk.h[3] = __float2bfloat16(fminf(fmaxf(rintf(v.w * wsc), -1.f), 1.f));
    reinterpret_cast<uint2*>(g_wq)[i] = pk.u;
}

// ---------------- Activation RMSNorm + int8 fake-quant ----------------
// R14-proven best: 128 threads/token, 4x float4 per thread -> 8
// independent LDG.128 in flight (MLP 8), 61us / 77% of DRAM peak.
__global__ __launch_bounds__(128) void act_quant_kernel(const float* __restrict__ x,
                                                        const float* __restrict__ gamma) {
    int token = blockIdx.x;
    int tid = threadIdx.x;
    const float4* xr = reinterpret_cast<const float4*>(x + (size_t)token * KDIM);
    const float4* gr = reinterpret_cast<const float4*>(gamma);

    float4 v[4], g4[4];
#pragma unroll
    for (int i = 0; i < 4; i++) v[i] = xr[tid + 128 * i];
#pragma unroll
    for (int i = 0; i < 4; i++) g4[i] = gr[tid + 128 * i];

    float xg[16];
    float ss = 0.f, am = 0.f;
#pragma unroll
    for (int i = 0; i < 4; i++) {
        xg[4 * i + 0] = v[i].x * g4[i].x;
        xg[4 * i + 1] = v[i].y * g4[i].y;
        xg[4 * i + 2] = v[i].z * g4[i].z;
        xg[4 * i + 3] = v[i].w * g4[i].w;
        ss += v[i].x * v[i].x + v[i].y * v[i].y + v[i].z * v[i].z + v[i].w * v[i].w;
        am = fmaxf(am, fmaxf(fmaxf(fabsf(xg[4 * i + 0]), fabsf(xg[4 * i + 1])),
                             fmaxf(fabsf(xg[4 * i + 2]), fabsf(xg[4 * i + 3]))));
    }

    ss = warp_sum(ss);
    am = warp_max(am);
    __shared__ float sss[4], sam[4], sbr[2];
    int wid = tid >> 5, lid = tid & 31;
    if (!lid) { sss[wid] = ss; sam[wid] = am; }
    __syncthreads();
    if (tid == 0) {
        float S = 0.f, A = 0.f;
#pragma unroll
        for (int i = 0; i < 4; i++) { S += sss[i]; A = fmaxf(A, sam[i]); }
        float rms = 1.0f / sqrtf(S * (1.0f / (float)KDIM) + 1e-6f);
        float ascale = 127.0f / (A * rms + 1e-5f);
        sbr[0] = rms; sbr[1] = ascale;
        g_inva[token] = 1.0f / ascale;
    }
    __syncthreads();
    float rms = sbr[0], asc = sbr[1];
    uint2* outp = reinterpret_cast<uint2*>(g_xq + (size_t)token * KDIM);
#pragma unroll
    for (int i = 0; i < 4; i++) {
        union { uint2 u; __nv_bfloat16 h[4]; } pk;
#pragma unroll
        for (int j = 0; j < 4; j++) {
            float q = rintf(xg[4 * i + j] * rms * asc);   // round-half-to-even = jnp.round
            q = fminf(fmaxf(q, -128.0f), 127.0f);
            pk.h[j] = __float2bfloat16(q);                 // exact: |q| <= 128
        }
        outp[tid + 128 * i] = pk.u;
    }
}

// =====================================================================
// GEMM: the proven R5 structure (128x128 CTA tile, BK=64 bf16 SW128,
// legacy HMMA m16n8k16, 8 warps = 4(M) x 2(N), warp tile 32x64,
// 2 CTAs/SM, front-loaded cp.async burst, plain LDSM->MMA order)
// with ONE change: the trailing per-chunk __syncthreads is removed.
// It is redundant: the top-of-loop barrier at iteration c+1 (placed
// after each thread's own cp.async.wait_group 0) already orders
// (a) all warps' chunk-c reads of buffer c&1 before load_chunk(c+2)
// overwrites it, and (b) cross-thread visibility of chunk c+1 data.
// One barrier per chunk instead of two -> less skew absorption.
// =====================================================================
#define BK 64                   // bf16 per K chunk (128 bytes, SW128 atom)
#define NK_ITERS (KDIM / BK)    // 32
#define A_BYTES 16384           // 128 rows x 128B
#define B_BYTES 16384
#define STAGE_BYTES (A_BYTES + B_BYTES)  // 32768
static constexpr unsigned GEMM_SMEM = 2 * STAGE_BYTES;  // 65536

__device__ __forceinline__ uint32_t smem_u32(const void* p) {
    uint32_t a;
    asm("{ .reg .u64 t; cvta.to.shared.u64 t, %1; cvt.u32.u64 %0, t; }" : "=r"(a) : "l"(p));
    return a;
}

__device__ __forceinline__ void cp_async16(uint32_t saddr, const void* gaddr) {
    asm volatile("cp.async.cg.shared.global [%0], [%1], 16;" :: "r"(saddr), "l"(gaddr));
}
__device__ __forceinline__ void cp_commit() { asm volatile("cp.async.commit_group;"); }
__device__ __forceinline__ void cp_wait_all() { asm volatile("cp.async.wait_group 0;"); }

__device__ __forceinline__ void ldmatrix_x4(uint32_t* r, uint32_t addr) {
    asm volatile("ldmatrix.sync.aligned.m8n8.x4.shared.b16 {%0,%1,%2,%3}, [%4];"
                 : "=r"(r[0]), "=r"(r[1]), "=r"(r[2]), "=r"(r[3]) : "r"(addr));
}

__device__ __forceinline__ void mma16816(float* d, const uint32_t* a, uint32_t b0, uint32_t b1) {
    asm volatile(
        "mma.sync.aligned.m16n8k16.row.col.f32.bf16.bf16.f32 "
        "{%0,%1,%2,%3}, {%4,%5,%6,%7}, {%8,%9}, {%0,%1,%2,%3};"
        : "+f"(d[0]), "+f"(d[1]), "+f"(d[2]), "+f"(d[3])
        : "r"(a[0]), "r"(a[1]), "r"(a[2]), "r"(a[3]), "r"(b0), "r"(b1));
}

__global__ __launch_bounds__(256, 2) void bitlinear_gemm(float* __restrict__ out) {
    extern __shared__ char smem[];
    const uint32_t base = smem_u32(smem);

    const int tid = threadIdx.x;
    const int wid = tid >> 5;
    const uint32_t lane = tid & 31;
    const int warp_m = wid >> 1;          // 0..3
    const int warp_n = wid & 1;           // 0..1
    const size_t tile_m = (size_t)blockIdx.y * 128;
    const size_t tile_n = (size_t)blockIdx.x * 128;

    const char* gA = reinterpret_cast<const char*>(g_xq) + tile_m * (KDIM * 2);
    const char* gB = reinterpret_cast<const char*>(g_wq) + tile_n * (KDIM * 2);

    // ---- loader precompute: A = 1024 16B units (4/thread), B same ----
    uint32_t st_sw[8];
    const char* gsrc[8];
#pragma unroll
    for (int j = 0; j < 4; j++) {
        int u = tid + j * 256;
        int row = u >> 3, q = u & 7;
        uint32_t off = (uint32_t)row * 128u + (uint32_t)q * 16u;
        uint32_t sw = off ^ ((off >> 3) & 0x70u);
        st_sw[j] = sw;                                  // A region (+0)
        st_sw[j + 4] = 16384u + sw;                     // B region (+16KB)
        gsrc[j]     = gA + (size_t)row * (KDIM * 2) + (size_t)q * 16u;
        gsrc[j + 4] = gB + (size_t)row * (KDIM * 2) + (size_t)q * 16u;
    }

    auto load_chunk = [&](int c, int buf) {
        uint32_t sb = base + (uint32_t)buf * STAGE_BYTES;
        size_t cb = (size_t)c * 128;
#pragma unroll
        for (int j = 0; j < 8; j++) cp_async16(sb + st_sw[j], gsrc[j] + cb);
        cp_commit();
    };

    // ---- ldmatrix base offsets (per lane) ----
    const uint32_t lrow = lane & 15;
    const uint32_t lcol = (lane >> 4) * 16;   // byte offset of 8-col half
    const uint32_t a_off0 = ((uint32_t)warp_m * 32u + lrow) * 128u + lcol;
    const uint32_t b_off0 = ((uint32_t)warp_n * 64u + lrow) * 128u + lcol;

    float acc[2][8][4];
#pragma unroll
    for (int mi = 0; mi < 2; mi++)
#pragma unroll
        for (int nj = 0; nj < 8; nj++)
#pragma unroll
            for (int i = 0; i < 4; i++) acc[mi][nj][i] = 0.f;

    load_chunk(0, 0);

    for (int c = 0; c < NK_ITERS; ++c) {
        int buf = c & 1;
        cp_wait_all();       // own group for chunk c complete
        __syncthreads();     // all threads' copies visible; all warps done reading buf (from c-1's prefetch target)
        if (c + 1 < NK_ITERS) load_chunk(c + 1, buf ^ 1);

        uint32_t sb = base + (uint32_t)buf * STAGE_BYTES;
#pragma unroll
        for (int ks = 0; ks < 4; ks++) {
            uint32_t kb = (uint32_t)ks * 32u;     // 16 bf16 = 32 bytes
            uint32_t af[2][4], bf[4][4];
#pragma unroll
            for (int mi = 0; mi < 2; mi++) {
                uint32_t off = a_off0 + (uint32_t)mi * 2048u + kb;
                ldmatrix_x4(af[mi], sb + (off ^ ((off >> 3) & 0x70u)));
            }
#pragma unroll
            for (int nj = 0; nj < 4; nj++) {
                uint32_t off = b_off0 + (uint32_t)nj * 2048u + kb;
                ldmatrix_x4(bf[nj], sb + 16384u + (off ^ ((off >> 3) & 0x70u)));
            }
#pragma unroll
            for (int mi = 0; mi < 2; mi++)
#pragma unroll
                for (int nj = 0; nj < 4; nj++) {
                    mma16816(acc[mi][nj * 2 + 0], af[mi], bf[nj][0], bf[nj][2]);
                    mma16816(acc[mi][nj * 2 + 1], af[mi], bf[nj][1], bf[nj][3]);
                }
        }
        // trailing __syncthreads removed: the next iteration's top barrier
        // (after cp.async.wait_group 0) provides the same ordering.
    }

    // ---- epilogue: dequant scale + store fp32 ----
    const float invw = g_ws[1];
    const int g = lane >> 2, cc = lane & 3;
#pragma unroll
    for (int mi = 0; mi < 2; mi++) {
        size_t r0 = tile_m + (size_t)(warp_m * 32 + mi * 16 + g);
        size_t r1 = r0 + 8;
        float s0 = g_inva[r0] * invw;
        float s1 = g_inva[r1] * invw;
        float* p0 = out + r0 * NDIM + tile_n + (size_t)(warp_n * 64 + cc * 2);
        float* p1 = out + r1 * NDIM + tile_n + (size_t)(warp_n * 64 + cc * 2);
#pragma unroll
        for (int nj = 0; nj < 8; nj++) {
            float2 v0 = make_float2(acc[mi][nj][0] * s0, acc[mi][nj][1] * s0);
            float2 v1 = make_float2(acc[mi][nj][2] * s1, acc[mi][nj][3] * s1);
            *reinterpret_cast<float2*>(p0 + nj * 8) = v0;
            *reinterpret_cast<float2*>(p1 + nj * 8) = v1;
        }
    }
}

// ---------------- Launch ----------------
extern "C" void kernel_launch(void* const* d_in, const int* in_sizes, int n_in,
                              void* d_out, int out_size) {
    const float* x     = reinterpret_cast<const float*>(d_in[0]);  // [4,8192,2048] fp32
    const float* gamma = reinterpret_cast<const float*>(d_in[1]);  // [2048] fp32
    const float* W     = reinterpret_cast<const float*>(d_in[2]);  // [2048,2048] fp32
    float* out = reinterpret_cast<float*>(d_out);

    cudaFuncSetAttribute(bitlinear_gemm, cudaFuncAttributeMaxDynamicSharedMemorySize, (int)GEMM_SMEM);

    w_rowabs_kernel<<<NDIM, 256>>>(W);
    w_scale_kernel<<<1, 256>>>();
    w_quant_kernel<<<(NDIM * KDIM) / (256 * 4), 256>>>(W);
    act_quant_kernel<<<M_TOK, 128>>>(x, gamma);

    dim3 grid(NDIM / 128, M_TOK / 128);  // (16, 256), x-fastest for A reuse in L2
    bitlinear_gemm<<<grid, 256, GEMM_SMEM>>>(out);
}

// round 17
// speedup vs baseline: 1.1354x; 1.0029x over previous
#include <cuda_runtime.h>
#include <cuda_bf16.h>
#include <cstdint>

// ---------------- Problem constants ----------------
#define M_TOK   32768      // B*S = 4*8192
#define KDIM    2048
#define NDIM    2048

// ---------------- Scratch (device globals; no allocation allowed) ----------------
__device__ __align__(256) static __nv_bfloat16 g_xq[(size_t)M_TOK * KDIM]; // 128 MB quantized activations (integer-valued bf16)
__device__ __align__(256) static __nv_bfloat16 g_wq[(size_t)NDIM * KDIM];  // 8 MB ternary weights (bf16 -1/0/1)
__device__ static float g_inva[M_TOK];   // per-token dequant scale 1/a_scale
__device__ static float g_rowabs[NDIM];  // per-row |W| sums
__device__ static float g_ws[2];         // [0] = w_scale, [1] = 1/w_scale = mean|W|+eps

// ---------------- Reductions ----------------
__device__ __forceinline__ float warp_sum(float v) {
#pragma unroll
    for (int o = 16; o; o >>= 1) v += __shfl_xor_sync(0xffffffffu, v, o);
    return v;
}
__device__ __forceinline__ float warp_max(float v) {
#pragma unroll
    for (int o = 16; o; o >>= 1) v = fmaxf(v, __shfl_xor_sync(0xffffffffu, v, o));
    return v;
}

// ---------------- Weight quantization ----------------
__global__ __launch_bounds__(256) void w_rowabs_kernel(const float* __restrict__ W) {
    int row = blockIdx.x, tid = threadIdx.x;
    const float4* wr = reinterpret_cast<const float4*>(W + (size_t)row * KDIM);
    float4 a = wr[2 * tid], b = wr[2 * tid + 1];
    float s = fabsf(a.x) + fabsf(a.y) + fabsf(a.z) + fabsf(a.w)
            + fabsf(b.x) + fabsf(b.y) + fabsf(b.z) + fabsf(b.w);
    s = warp_sum(s);
    __shared__ float ws[8];
    if (!(tid & 31)) ws[tid >> 5] = s;
    __syncthreads();
    if (tid == 0) {
        float t = 0.f;
#pragma unroll
        for (int i = 0; i < 8; i++) t += ws[i];
        g_rowabs[row] = t;
    }
}

__global__ __launch_bounds__(256) void w_scale_kernel() {
    int tid = threadIdx.x;
    float s = 0.f;
    for (int i = tid; i < NDIM; i += 256) s += g_rowabs[i];
    s = warp_sum(s);
    __shared__ float ws[8];
    if (!(tid & 31)) ws[tid >> 5] = s;
    __syncthreads();
    if (tid == 0) {
        float t = 0.f;
#pragma unroll
        for (int i = 0; i < 8; i++) t += ws[i];
        float mean = t * (1.0f / ((float)NDIM * (float)KDIM));
        g_ws[0] = 1.0f / (mean + 1e-5f);  // w_scale
        g_ws[1] = mean + 1e-5f;           // 1/w_scale
    }
}

__global__ __launch_bounds__(256) void w_quant_kernel(const float* __restrict__ W) {
    float wsc = g_ws[0];
    int i = blockIdx.x * 256 + threadIdx.x;  // over 1M float4
    float4 v = reinterpret_cast<const float4*>(W)[i];
    union { uint2 u; __nv_bfloat16 h[4]; } pk;
    pk.h[0] = __float2bfloat16(fminf(fmaxf(rintf(v.x * wsc), -1.f), 1.f));
    pk.h[1] = __float2bfloat16(fminf(fmaxf(rintf(v.y * wsc), -1.f), 1.f));
    pk.h[2] = __float2bfloat16(fminf(fmaxf(rintf(v.z * wsc), -1.f), 1.f));
    pk.h[3] = __float2bfloat16(fminf(fmaxf(rintf(v.w * wsc), -1.f), 1.f));
    reinterpret_cast<uint2*>(g_wq)[i] = pk.u;
}

// ---------------- Activation RMSNorm + int8 fake-quant ----------------
// 2 tokens per 128-thread block, ALL loads front-batched: 4 float4 of
// token0 + 4 of token1 + 4 gamma float4 issue before any math ->
// ~12 independent LDG.128 in flight per thread (MLP ~12 vs 8 in R16).
// Per-token reduction tree identical to the R14/R16 proven version.
__global__ __launch_bounds__(128) void act_quant_kernel(const float* __restrict__ x,
                                                        const float* __restrict__ gamma) {
    const int t0 = blockIdx.x * 2;
    const int tid = threadIdx.x;
    const float4* xr0 = reinterpret_cast<const float4*>(x + (size_t)t0 * KDIM);
    const float4* xr1 = reinterpret_cast<const float4*>(x + (size_t)(t0 + 1) * KDIM);
    const float4* gr  = reinterpret_cast<const float4*>(gamma);

    float4 va[4], vb[4], g4[4];
#pragma unroll
    for (int i = 0; i < 4; i++) va[i] = xr0[tid + 128 * i];
#pragma unroll
    for (int i = 0; i < 4; i++) vb[i] = xr1[tid + 128 * i];
#pragma unroll
    for (int i = 0; i < 4; i++) g4[i] = gr[tid + 128 * i];

    float xga[16], xgb[16];
    float ssa = 0.f, ama = 0.f, ssb = 0.f, amb = 0.f;
#pragma unroll
    for (int i = 0; i < 4; i++) {
        xga[4 * i + 0] = va[i].x * g4[i].x;
        xga[4 * i + 1] = va[i].y * g4[i].y;
        xga[4 * i + 2] = va[i].z * g4[i].z;
        xga[4 * i + 3] = va[i].w * g4[i].w;
        ssa += va[i].x * va[i].x + va[i].y * va[i].y + va[i].z * va[i].z + va[i].w * va[i].w;
        ama = fmaxf(ama, fmaxf(fmaxf(fabsf(xga[4 * i + 0]), fabsf(xga[4 * i + 1])),
                               fmaxf(fabsf(xga[4 * i + 2]), fabsf(xga[4 * i + 3]))));
    }
#pragma unroll
    for (int i = 0; i < 4; i++) {
        xgb[4 * i + 0] = vb[i].x * g4[i].x;
        xgb[4 * i + 1] = vb[i].y * g4[i].y;
        xgb[4 * i + 2] = vb[i].z * g4[i].z;
        xgb[4 * i + 3] = vb[i].w * g4[i].w;
        ssb += vb[i].x * vb[i].x + vb[i].y * vb[i].y + vb[i].z * vb[i].z + vb[i].w * vb[i].w;
        amb = fmaxf(amb, fmaxf(fmaxf(fabsf(xgb[4 * i + 0]), fabsf(xgb[4 * i + 1])),
                               fmaxf(fabsf(xgb[4 * i + 2]), fabsf(xgb[4 * i + 3]))));
    }

    ssa = warp_sum(ssa);  ama = warp_max(ama);
    ssb = warp_sum(ssb);  amb = warp_max(amb);
    __shared__ float sss[2][4], sam[2][4], sbr[2][2];
    int wid = tid >> 5, lid = tid & 31;
    if (!lid) { sss[0][wid] = ssa; sam[0][wid] = ama; sss[1][wid] = ssb; sam[1][wid] = amb; }
    __syncthreads();
    if (tid < 2) {   // thread 0 -> token0, thread 1 -> token1
        float S = 0.f, A = 0.f;
#pragma unroll
        for (int i = 0; i < 4; i++) { S += sss[tid][i]; A = fmaxf(A, sam[tid][i]); }
        float rms = 1.0f / sqrtf(S * (1.0f / (float)KDIM) + 1e-6f);
        float ascale = 127.0f / (A * rms + 1e-5f);
        sbr[tid][0] = rms; sbr[tid][1] = ascale;
        g_inva[t0 + tid] = 1.0f / ascale;
    }
    __syncthreads();

    {
        float rms = sbr[0][0], asc = sbr[0][1];
        uint2* outp = reinterpret_cast<uint2*>(g_xq + (size_t)t0 * KDIM);
#pragma unroll
        for (int i = 0; i < 4; i++) {
            union { uint2 u; __nv_bfloat16 h[4]; } pk;
#pragma unroll
            for (int j = 0; j < 4; j++) {
                float q = rintf(xga[4 * i + j] * rms * asc);  // round-half-to-even = jnp.round
                q = fminf(fmaxf(q, -128.0f), 127.0f);
                pk.h[j] = __float2bfloat16(q);                 // exact: |q| <= 128
            }
            outp[tid + 128 * i] = pk.u;
        }
    }
    {
        float rms = sbr[1][0], asc = sbr[1][1];
        uint2* outp = reinterpret_cast<uint2*>(g_xq + (size_t)(t0 + 1) * KDIM);
#pragma unroll
        for (int i = 0; i < 4; i++) {
            union { uint2 u; __nv_bfloat16 h[4]; } pk;
#pragma unroll
            for (int j = 0; j < 4; j++) {
                float q = rintf(xgb[4 * i + j] * rms * asc);
                q = fminf(fmaxf(q, -128.0f), 127.0f);
                pk.h[j] = __float2bfloat16(q);
            }
            outp[tid + 128 * i] = pk.u;
        }
    }
}

// =====================================================================
// GEMM: byte-identical to the R16 702.6us winner.
// 128x128 CTA tile, BK=64 bf16 SW128, legacy HMMA m16n8k16, 8 warps =
// 4(M) x 2(N), warp tile 32x64, 2 CTAs/SM, front-loaded cp.async burst,
// plain LDSM->MMA order, ONE barrier per chunk (trailing sync removed —
// the next top-of-loop barrier provides the same ordering).
// At the measured L1-crossbar/L2 floor; do not touch.
// =====================================================================
#define BK 64                   // bf16 per K chunk (128 bytes, SW128 atom)
#define NK_ITERS (KDIM / BK)    // 32
#define A_BYTES 16384           // 128 rows x 128B
#define B_BYTES 16384
#define STAGE_BYTES (A_BYTES + B_BYTES)  // 32768
static constexpr unsigned GEMM_SMEM = 2 * STAGE_BYTES;  // 65536

__device__ __forceinline__ uint32_t smem_u32(const void* p) {
    uint32_t a;
    asm("{ .reg .u64 t; cvta.to.shared.u64 t, %1; cvt.u32.u64 %0, t; }" : "=r"(a) : "l"(p));
    return a;
}

__device__ __forceinline__ void cp_async16(uint32_t saddr, const void* gaddr) {
    asm volatile("cp.async.cg.shared.global [%0], [%1], 16;" :: "r"(saddr), "l"(gaddr));
}
__device__ __forceinline__ void cp_commit() { asm volatile("cp.async.commit_group;"); }
__device__ __forceinline__ void cp_wait_all() { asm volatile("cp.async.wait_group 0;"); }

__device__ __forceinline__ void ldmatrix_x4(uint32_t* r, uint32_t addr) {
    asm volatile("ldmatrix.sync.aligned.m8n8.x4.shared.b16 {%0,%1,%2,%3}, [%4];"
                 : "=r"(r[0]), "=r"(r[1]), "=r"(r[2]), "=r"(r[3]) : "r"(addr));
}

__device__ __forceinline__ void mma16816(float* d, const uint32_t* a, uint32_t b0, uint32_t b1) {
    asm volatile(
        "mma.sync.aligned.m16n8k16.row.col.f32.bf16.bf16.f32 "
        "{%0,%1,%2,%3}, {%4,%5,%6,%7}, {%8,%9}, {%0,%1,%2,%3};"
        : "+f"(d[0]), "+f"(d[1]), "+f"(d[2]), "+f"(d[3])
        : "r"(a[0]), "r"(a[1]), "r"(a[2]), "r"(a[3]), "r"(b0), "r"(b1));
}

__global__ __launch_bounds__(256, 2) void bitlinear_gemm(float* __restrict__ out) {
    extern __shared__ char smem[];
    const uint32_t base = smem_u32(smem);

    const int tid = threadIdx.x;
    const int wid = tid >> 5;
    const uint32_t lane = tid & 31;
    const int warp_m = wid >> 1;          // 0..3
    const int warp_n = wid & 1;           // 0..1
    const size_t tile_m = (size_t)blockIdx.y * 128;
    const size_t tile_n = (size_t)blockIdx.x * 128;

    const char* gA = reinterpret_cast<const char*>(g_xq) + tile_m * (KDIM * 2);
    const char* gB = reinterpret_cast<const char*>(g_wq) + tile_n * (KDIM * 2);

    // ---- loader precompute: A = 1024 16B units (4/thread), B same ----
    uint32_t st_sw[8];
    const char* gsrc[8];
#pragma unroll
    for (int j = 0; j < 4; j++) {
        int u = tid + j * 256;
        int row = u >> 3, q = u & 7;
        uint32_t off = (uint32_t)row * 128u + (uint32_t)q * 16u;
        uint32_t sw = off ^ ((off >> 3) & 0x70u);
        st_sw[j] = sw;                                  // A region (+0)
        st_sw[j + 4] = 16384u + sw;                     // B region (+16KB)
        gsrc[j]     = gA + (size_t)row * (KDIM * 2) + (size_t)q * 16u;
        gsrc[j + 4] = gB + (size_t)row * (KDIM * 2) + (size_t)q * 16u;
    }

    auto load_chunk = [&](int c, int buf) {
        uint32_t sb = base + (uint32_t)buf * STAGE_BYTES;
        size_t cb = (size_t)c * 128;
#pragma unroll
        for (int j = 0; j < 8; j++) cp_async16(sb + st_sw[j], gsrc[j] + cb);
        cp_commit();
    };

    // ---- ldmatrix base offsets (per lane) ----
    const uint32_t lrow = lane & 15;
    const uint32_t lcol = (lane >> 4) * 16;   // byte offset of 8-col half
    const uint32_t a_off0 = ((uint32_t)warp_m * 32u + lrow) * 128u + lcol;
    const uint32_t b_off0 = ((uint32_t)warp_n * 64u + lrow) * 128u + lcol;

    float acc[2][8][4];
#pragma unroll
    for (int mi = 0; mi < 2; mi++)
#pragma unroll
        for (int nj = 0; nj < 8; nj++)
#pragma unroll
            for (int i = 0; i < 4; i++) acc[mi][nj][i] = 0.f;

    load_chunk(0, 0);

    for (int c = 0; c < NK_ITERS; ++c) {
        int buf = c & 1;
        cp_wait_all();       // own group for chunk c complete
        __syncthreads();     // copies visible; all warps done reading the other buffer
        if (c + 1 < NK_ITERS) load_chunk(c + 1, buf ^ 1);

        uint32_t sb = base + (uint32_t)buf * STAGE_BYTES;
#pragma unroll
        for (int ks = 0; ks < 4; ks++) {
            uint32_t kb = (uint32_t)ks * 32u;     // 16 bf16 = 32 bytes
            uint32_t af[2][4], bf[4][4];
#pragma unroll
            for (int mi = 0; mi < 2; mi++) {
                uint32_t off = a_off0 + (uint32_t)mi * 2048u + kb;
                ldmatrix_x4(af[mi], sb + (off ^ ((off >> 3) & 0x70u)));
            }
#pragma unroll
            for (int nj = 0; nj < 4; nj++) {
                uint32_t off = b_off0 + (uint32_t)nj * 2048u + kb;
                ldmatrix_x4(bf[nj], sb + 16384u + (off ^ ((off >> 3) & 0x70u)));
            }
#pragma unroll
            for (int mi = 0; mi < 2; mi++)
#pragma unroll
                for (int nj = 0; nj < 4; nj++) {
                    mma16816(acc[mi][nj * 2 + 0], af[mi], bf[nj][0], bf[nj][2]);
                    mma16816(acc[mi][nj * 2 + 1], af[mi], bf[nj][1], bf[nj][3]);
                }
        }
    }

    // ---- epilogue: dequant scale + store fp32 ----
    const float invw = g_ws[1];
    const int g = lane >> 2, cc = lane & 3;
#pragma unroll
    for (int mi = 0; mi < 2; mi++) {
        size_t r0 = tile_m + (size_t)(warp_m * 32 + mi * 16 + g);
        size_t r1 = r0 + 8;
        float s0 = g_inva[r0] * invw;
        float s1 = g_inva[r1] * invw;
        float* p0 = out + r0 * NDIM + tile_n + (size_t)(warp_n * 64 + cc * 2);
        float* p1 = out + r1 * NDIM + tile_n + (size_t)(warp_n * 64 + cc * 2);
#pragma unroll
        for (int nj = 0; nj < 8; nj++) {
            float2 v0 = make_float2(acc[mi][nj][0] * s0, acc[mi][nj][1] * s0);
            float2 v1 = make_float2(acc[mi][nj][2] * s1, acc[mi][nj][3] * s1);
            *reinterpret_cast<float2*>(p0 + nj * 8) = v0;
            *reinterpret_cast<float2*>(p1 + nj * 8) = v1;
        }
    }
}

// ---------------- Launch ----------------
extern "C" void kernel_launch(void* const* d_in, const int* in_sizes, int n_in,
                              void* d_out, int out_size) {
    const float* x     = reinterpret_cast<const float*>(d_in[0]);  // [4,8192,2048] fp32
    const float* gamma = reinterpret_cast<const float*>(d_in[1]);  // [2048] fp32
    const float* W     = reinterpret_cast<const float*>(d_in[2]);  // [2048,2048] fp32
    float* out = reinterpret_cast<float*>(d_out);

    cudaFuncSetAttribute(bitlinear_gemm, cudaFuncAttributeMaxDynamicSharedMemorySize, (int)GEMM_SMEM);

    w_rowabs_kernel<<<NDIM, 256>>>(W);
    w_scale_kernel<<<1, 256>>>();
    w_quant_kernel<<<(NDIM * KDIM) / (256 * 4), 256>>>(W);
    act_quant_kernel<<<M_TOK / 2, 128>>>(x, gamma);

    dim3 grid(NDIM / 128, M_TOK / 128);  // (16, 256), x-fastest for A reuse in L2
    bitlinear_gemm<<<grid, 256, GEMM_SMEM>>>(out);
}